// round 2
// baseline (speedup 1.0000x reference)
#include <cuda_runtime.h>
#include <cstdint>

#define FULL_MASK 0xFFFFFFFFu

// ---------------- packed f32x2 helpers (sm_100+/sm_103a PTX) ----------------
__device__ __forceinline__ unsigned long long pack2(float lo, float hi) {
    unsigned long long r;
    asm("mov.b64 %0, {%1, %2};" : "=l"(r) : "f"(lo), "f"(hi));
    return r;
}
__device__ __forceinline__ void unpack2(unsigned long long v, float& lo, float& hi) {
    asm("mov.b64 {%0, %1}, %2;" : "=f"(lo), "=f"(hi) : "l"(v));
}
__device__ __forceinline__ unsigned long long ffma2(unsigned long long a,
                                                    unsigned long long b,
                                                    unsigned long long c) {
    unsigned long long d;
    asm("fma.rn.f32x2 %0, %1, %2, %3;" : "=l"(d) : "l"(a), "l"(b), "l"(c));
    return d;
}

// ---------------- model constants ----------------
__constant__ int FOFF[23] = {0,4,8,12,16,20,24,28,32,36,40,44,48,50,52,53,57,58,59,60,61,62,63};
__constant__ int FDIM[23] = {4,4,4,4,4,4,4,4,4,4,4,4, 2, 2, 1, 4, 1, 1, 1, 1, 1, 1, 2};

static constexpr int OBS   = 65;
static constexpr int NF    = 23;
static constexpr int EMB   = 10;
static constexpr int ZDIM  = 230;   // NF * EMB
static constexpr int HID   = 164;
static constexpr int TILE_B = 64;   // rows per CTA
static constexpr int RS    = 66;    // padded row stride in smem ([k][row] layout)

// smem float offsets
static constexpr int ZB_OFF  = 0;                 // 230 x 66
static constexpr int BB_OFF  = ZDIM * RS;         // 164 x 66
static constexpr int SCR_OFF = BB_OFF + HID * RS; // per-warp scratch
static constexpr int WSZ     = 68 + 232 * 4 + 32; // xb,hb,qb,kb,vb,ob = 1028 floats
static constexpr int SMEM_FLOATS = SCR_OFF + 8 * WSZ;

__global__ void __launch_bounds__(256, 1)
actor_kernel(const float* __restrict__ x,
             const float* __restrict__ Wp,  const float* __restrict__ bp,
             const float* __restrict__ Wq,  const float* __restrict__ Wk,
             const float* __restrict__ Wv,
             const float* __restrict__ W1,  const float* __restrict__ b1,
             const float* __restrict__ W2,  const float* __restrict__ b2,
             const float* __restrict__ W3,  const float* __restrict__ b3,
             const float* __restrict__ W4,  const float* __restrict__ b4,
             const float* __restrict__ W5,  const float* __restrict__ b5,
             const float* __restrict__ Wm,  const float* __restrict__ bm,
             const float* __restrict__ Wmk, const float* __restrict__ bmk,
             float* __restrict__ out, int B)
{
    extern __shared__ float sm[];
    float* zb = sm + ZB_OFF;
    float* bb = sm + BB_OFF;

    const int tid  = threadIdx.x;
    const int w    = tid >> 5;
    const int lane = tid & 31;
    float* ws = sm + SCR_OFF + w * WSZ;
    float* xb = ws;            // 68
    float* hb = ws + 68;       // 232
    float* qb = hb + 232;      // 232
    float* kb = qb + 232;      // 232
    float* vb = kb + 232;      // 232
    float* ob = vb + 232;      // 32

    const int rowbase = blockIdx.x * TILE_B;
    const int r0 = w * 8;      // this warp owns local rows [r0, r0+8)

    // ======================= Phase 1: proj + attention (per row) ===========
    const float inv_sqrt10 = 0.31622776601683794f;
    for (int rr = 0; rr < 8; rr++) {
        const int row = rowbase + r0 + rr;
        // load x row
        for (int i = lane; i < OBS; i += 32) xb[i] = x[row * OBS + i];
        __syncwarp();
        // block-diagonal projection -> h[230]
        for (int idx = lane; idx < ZDIM; idx += 32) {
            const int f   = idx / 10;
            const int off = FOFF[f];
            const int dim = FDIM[f];
            float a = bp[idx];
            for (int d = 0; d < dim; d++)
                a = fmaf(xb[off + d], Wp[(off + d) * ZDIM + idx], a);
            hb[idx] = a;
        }
        __syncwarp();
        // q, k, v
        for (int idx = lane; idx < ZDIM; idx += 32) {
            const int i = idx / 10;
            const int e = idx - i * 10;
            float aq = 0.f, ak = 0.f, av = 0.f;
            #pragma unroll
            for (int d = 0; d < 10; d++) {
                const float hv = hb[i * 10 + d];
                aq = fmaf(hv, Wq[d * 10 + e], aq);
                ak = fmaf(hv, Wk[d * 10 + e], ak);
                av = fmaf(hv, Wv[d * 10 + e], av);
            }
            qb[idx] = aq; kb[idx] = ak; vb[idx] = av;
        }
        __syncwarp();
        // attention: per query token i, lanes j cover keys
        for (int i = 0; i < NF; i++) {
            float lg = -1e30f;
            if (lane < NF) {
                float a = 0.f;
                #pragma unroll
                for (int e = 0; e < 10; e++)
                    a = fmaf(qb[i * 10 + e], kb[lane * 10 + e], a);
                lg = a * inv_sqrt10;
            }
            float m = lg;
            #pragma unroll
            for (int o = 16; o; o >>= 1) m = fmaxf(m, __shfl_xor_sync(FULL_MASK, m, o));
            float p = (lane < NF) ? __expf(lg - m) : 0.f;
            float s = p;
            #pragma unroll
            for (int o = 16; o; o >>= 1) s += __shfl_xor_sync(FULL_MASK, s, o);
            if (lane < NF) ob[lane] = p / s;
            __syncwarp();
            if (lane < EMB) {
                float c = 0.f;
                #pragma unroll
                for (int j = 0; j < NF; j++)
                    c = fmaf(ob[j], vb[j * 10 + lane], c);
                hb[i * 10 + lane] += c;   // residual: z = h + ctx
            }
            __syncwarp();
        }
        // z -> zbuf in [k][row] layout
        for (int idx = lane; idx < ZDIM; idx += 32)
            zb[idx * RS + r0 + rr] = hb[idx];
        __syncwarp();
    }

    // ======================= Phase 2: MLP (warp-local 8-row GEMMs) =========
    // acc layout: 4 row-pairs x 6 column slots, packed f32x2 over row pairs.
    auto gemm = [&](const float* sin, int K, const float* W, const float* bias,
                    float* sout, bool relu) {
        unsigned long long acc[4][6];
        int c[6];
        #pragma unroll
        for (int cc = 0; cc < 6; cc++) {
            c[cc] = lane + 32 * cc;
            const float bv = (c[cc] < HID) ? bias[c[cc]] : 0.f;
            const unsigned long long b2v = pack2(bv, bv);
            #pragma unroll
            for (int p = 0; p < 4; p++) acc[p][cc] = b2v;
        }
        #pragma unroll 2
        for (int k = 0; k < K; k++) {
            const float* zr = sin + k * RS + r0;   // 8B-aligned (RS even, r0 even)
            const unsigned long long z0 = *(const unsigned long long*)(zr + 0);
            const unsigned long long z1 = *(const unsigned long long*)(zr + 2);
            const unsigned long long z2 = *(const unsigned long long*)(zr + 4);
            const unsigned long long z3 = *(const unsigned long long*)(zr + 6);
            const float* wrow = W + k * HID;
            #pragma unroll
            for (int cc = 0; cc < 6; cc++) {
                const int cl = (c[cc] < HID) ? c[cc] : (HID - 1);
                const float wv = wrow[cl];
                const unsigned long long w2 = pack2(wv, wv);
                acc[0][cc] = ffma2(z0, w2, acc[0][cc]);
                acc[1][cc] = ffma2(z1, w2, acc[1][cc]);
                acc[2][cc] = ffma2(z2, w2, acc[2][cc]);
                acc[3][cc] = ffma2(z3, w2, acc[3][cc]);
            }
        }
        #pragma unroll
        for (int cc = 0; cc < 6; cc++) {
            if (c[cc] < HID) {
                #pragma unroll
                for (int p = 0; p < 4; p++) {
                    float lo, hi;
                    unpack2(acc[p][cc], lo, hi);
                    if (relu) { lo = fmaxf(lo, 0.f); hi = fmaxf(hi, 0.f); }
                    *(float2*)&sout[c[cc] * RS + r0 + 2 * p] = make_float2(lo, hi);
                }
            }
        }
        __syncwarp();
    };

    gemm(zb, ZDIM, W1, b1, bb, true);
    gemm(bb, HID,  W2, b2, zb, true);
    gemm(zb, HID,  W3, b3, bb, true);
    gemm(bb, HID,  W4, b4, zb, true);
    gemm(zb, HID,  W5, b5, bb, true);

    // ======================= Heads: move[5], mark[1] ========================
    // 48 work items per warp (8 rows x 6 outputs) on 32 lanes -> strided loop.
    for (int t = lane; t < 48; t += 32) {
        const int r  = t / 6;      // row within warp group (0..7)
        const int cc = t % 6;      // 0..4 move, 5 mark
        const int row = rowbase + r0 + r;
        const float* zz = bb + r0 + r;
        if (cc < 5) {
            float a = bm[cc];
            #pragma unroll 4
            for (int k = 0; k < HID; k++) a = fmaf(zz[k * RS], Wm[k * 5 + cc], a);
            out[row * 5 + cc] = a;
        } else {
            float a = bmk[0];
            #pragma unroll 4
            for (int k = 0; k < HID; k++) a = fmaf(zz[k * RS], Wmk[k], a);
            out[(long long)B * 5 + row] = a;
        }
    }
}

extern "C" void kernel_launch(void* const* d_in, const int* in_sizes, int n_in,
                              void* d_out, int out_size) {
    const float* x   = (const float*)d_in[0];
    const float* Wp  = (const float*)d_in[1];
    const float* bp  = (const float*)d_in[2];
    const float* Wq  = (const float*)d_in[3];
    const float* Wk  = (const float*)d_in[4];
    const float* Wv  = (const float*)d_in[5];
    const float* W1  = (const float*)d_in[6];
    const float* b1  = (const float*)d_in[7];
    const float* W2  = (const float*)d_in[8];
    const float* b2  = (const float*)d_in[9];
    const float* W3  = (const float*)d_in[10];
    const float* b3  = (const float*)d_in[11];
    const float* W4  = (const float*)d_in[12];
    const float* b4  = (const float*)d_in[13];
    const float* W5  = (const float*)d_in[14];
    const float* b5  = (const float*)d_in[15];
    const float* Wm  = (const float*)d_in[16];
    const float* bm  = (const float*)d_in[17];
    const float* Wmk = (const float*)d_in[18];
    const float* bmk = (const float*)d_in[19];
    float* out = (float*)d_out;

    const int B = in_sizes[0] / OBS;            // 131072
    const int smem_bytes = SMEM_FLOATS * 4;     // ~136.9 KB

    cudaFuncSetAttribute(actor_kernel,
                         cudaFuncAttributeMaxDynamicSharedMemorySize,
                         smem_bytes);

    actor_kernel<<<B / TILE_B, 256, smem_bytes>>>(
        x, Wp, bp, Wq, Wk, Wv,
        W1, b1, W2, b2, W3, b3, W4, b4, W5, b5,
        Wm, bm, Wmk, bmk, out, B);
}

// round 3
// speedup vs baseline: 1.3623x; 1.3623x over previous
#include <cuda_runtime.h>
#include <cstdint>

#define FULL_MASK 0xFFFFFFFFu

// ---------------- packed f32x2 helpers (sm_100+/sm_103a PTX) ----------------
__device__ __forceinline__ unsigned long long pack2(float lo, float hi) {
    unsigned long long r;
    asm("mov.b64 %0, {%1, %2};" : "=l"(r) : "f"(lo), "f"(hi));
    return r;
}
__device__ __forceinline__ void unpack2(unsigned long long v, float& lo, float& hi) {
    asm("mov.b64 {%0, %1}, %2;" : "=f"(lo), "=f"(hi) : "l"(v));
}
__device__ __forceinline__ unsigned long long ffma2(unsigned long long a,
                                                    unsigned long long b,
                                                    unsigned long long c) {
    unsigned long long d;
    asm("fma.rn.f32x2 %0, %1, %2, %3;" : "=l"(d) : "l"(a), "l"(b), "l"(c));
    return d;
}

// ---------------- model constants ----------------
__constant__ int FOFF[23] = {0,4,8,12,16,20,24,28,32,36,40,44,48,50,52,53,57,58,59,60,61,62,63};
__constant__ int FDIM[23] = {4,4,4,4,4,4,4,4,4,4,4,4, 2, 2, 1, 4, 1, 1, 1, 1, 1, 1, 2};

static constexpr int OBS   = 65;
static constexpr int NF    = 23;
static constexpr int EMB   = 10;
static constexpr int ZDIM  = 230;   // NF * EMB
static constexpr int HID   = 164;
static constexpr int TILE_B = 32;   // rows per CTA (4 per warp)
static constexpr int RS    = 34;    // padded row stride in smem ([k][row] layout)

// smem float offsets
static constexpr int ZB_OFF  = 0;                 // 230 x 34
static constexpr int BB_OFF  = ZDIM * RS;         // 164 x 34
static constexpr int SCR_OFF = BB_OFF + HID * RS; // per-warp scratch
static constexpr int WSZ     = 68 + 232 * 4 + 32; // xb,hb,qb,kb,vb,ob = 1028 floats
static constexpr int SMEM_FLOATS = SCR_OFF + 8 * WSZ;   // 13396 + 8224 = 21620 (~86.5 KB)

__global__ void __launch_bounds__(256, 2)
actor_kernel(const float* __restrict__ x,
             const float* __restrict__ Wp,  const float* __restrict__ bp,
             const float* __restrict__ Wq,  const float* __restrict__ Wk,
             const float* __restrict__ Wv,
             const float* __restrict__ W1,  const float* __restrict__ b1,
             const float* __restrict__ W2,  const float* __restrict__ b2,
             const float* __restrict__ W3,  const float* __restrict__ b3,
             const float* __restrict__ W4,  const float* __restrict__ b4,
             const float* __restrict__ W5,  const float* __restrict__ b5,
             const float* __restrict__ Wm,  const float* __restrict__ bm,
             const float* __restrict__ Wmk, const float* __restrict__ bmk,
             float* __restrict__ out, int B)
{
    extern __shared__ float sm[];
    float* zb = sm + ZB_OFF;
    float* bb = sm + BB_OFF;

    const int tid  = threadIdx.x;
    const int w    = tid >> 5;
    const int lane = tid & 31;
    float* ws = sm + SCR_OFF + w * WSZ;
    float* xb = ws;            // 68
    float* hb = ws + 68;       // 232
    float* qb = hb + 232;      // 232
    float* kb = qb + 232;      // 232
    float* vb = kb + 232;      // 232
    float* ob = vb + 232;      // 32

    const int rowbase = blockIdx.x * TILE_B;
    const int r0 = w * 4;      // this warp owns local rows [r0, r0+4)

    // ======================= Phase 1: proj + attention (per row) ===========
    const float inv_sqrt10 = 0.31622776601683794f;
    for (int rr = 0; rr < 4; rr++) {
        const int row = rowbase + r0 + rr;
        // load x row
        for (int i = lane; i < OBS; i += 32) xb[i] = x[row * OBS + i];
        __syncwarp();
        // block-diagonal projection -> h[230]
        for (int idx = lane; idx < ZDIM; idx += 32) {
            const int f   = idx / 10;
            const int off = FOFF[f];
            const int dim = FDIM[f];
            float a = bp[idx];
            for (int d = 0; d < dim; d++)
                a = fmaf(xb[off + d], Wp[(off + d) * ZDIM + idx], a);
            hb[idx] = a;
        }
        __syncwarp();
        // q, k, v
        for (int idx = lane; idx < ZDIM; idx += 32) {
            const int i = idx / 10;
            const int e = idx - i * 10;
            float aq = 0.f, ak = 0.f, av = 0.f;
            #pragma unroll
            for (int d = 0; d < 10; d++) {
                const float hv = hb[i * 10 + d];
                aq = fmaf(hv, Wq[d * 10 + e], aq);
                ak = fmaf(hv, Wk[d * 10 + e], ak);
                av = fmaf(hv, Wv[d * 10 + e], av);
            }
            qb[idx] = aq; kb[idx] = ak; vb[idx] = av;
        }
        __syncwarp();
        // attention: per query token i, lanes j cover keys
        for (int i = 0; i < NF; i++) {
            float lg = -1e30f;
            if (lane < NF) {
                float a = 0.f;
                #pragma unroll
                for (int e = 0; e < 10; e++)
                    a = fmaf(qb[i * 10 + e], kb[lane * 10 + e], a);
                lg = a * inv_sqrt10;
            }
            float m = lg;
            #pragma unroll
            for (int o = 16; o; o >>= 1) m = fmaxf(m, __shfl_xor_sync(FULL_MASK, m, o));
            float p = (lane < NF) ? __expf(lg - m) : 0.f;
            float s = p;
            #pragma unroll
            for (int o = 16; o; o >>= 1) s += __shfl_xor_sync(FULL_MASK, s, o);
            if (lane < NF) ob[lane] = p / s;
            __syncwarp();
            if (lane < EMB) {
                float c = 0.f;
                #pragma unroll
                for (int j = 0; j < NF; j++)
                    c = fmaf(ob[j], vb[j * 10 + lane], c);
                hb[i * 10 + lane] += c;   // residual: z = h + ctx
            }
            __syncwarp();
        }
        // z -> zbuf in [k][row] layout
        for (int idx = lane; idx < ZDIM; idx += 32)
            zb[idx * RS + r0 + rr] = hb[idx];
        __syncwarp();
    }

    // ======================= Phase 2: MLP (warp-local 4-row GEMMs) =========
    // FFMA2 packed over COLUMN pairs: lane owns cols (64*cc + 2*lane, +1).
    // Weight pair loads are a single LDG.64 (contiguous columns).
    auto gemm = [&](const float* sin, int K, const float* W, const float* bias,
                    float* sout, bool relu) {
        unsigned long long acc[4][3];
        int  c0[3];
        bool valid[3];
        #pragma unroll
        for (int cc = 0; cc < 3; cc++) {
            c0[cc]    = 64 * cc + 2 * lane;
            valid[cc] = (c0[cc] < HID);          // c0 even, so c0<164 => both cols valid
            unsigned long long b2v = 0;
            if (valid[cc]) {
                const float2 bv = *(const float2*)&bias[c0[cc]];
                b2v = pack2(bv.x, bv.y);
            }
            #pragma unroll
            for (int r = 0; r < 4; r++) acc[r][cc] = b2v;
        }
        const int cl2 = valid[2] ? c0[2] : 160;  // clamped addr for inactive lanes
        #pragma unroll 2
        for (int k = 0; k < K; k++) {
            const float* zr = sin + k * RS + r0;     // 8B-aligned (RS,r0 even)
            const float2 zp0 = *(const float2*)(zr);
            const float2 zp1 = *(const float2*)(zr + 2);
            const unsigned long long z0 = pack2(zp0.x, zp0.x);
            const unsigned long long z1 = pack2(zp0.y, zp0.y);
            const unsigned long long z2 = pack2(zp1.x, zp1.x);
            const unsigned long long z3 = pack2(zp1.y, zp1.y);
            const float* wrow = W + k * HID;         // row stride 164 (even) -> 8B aligned
            const unsigned long long w0 = *(const unsigned long long*)(wrow + c0[0]);
            const unsigned long long w1 = *(const unsigned long long*)(wrow + c0[1]);
            const unsigned long long w2 = *(const unsigned long long*)(wrow + cl2);
            acc[0][0] = ffma2(z0, w0, acc[0][0]);
            acc[1][0] = ffma2(z1, w0, acc[1][0]);
            acc[2][0] = ffma2(z2, w0, acc[2][0]);
            acc[3][0] = ffma2(z3, w0, acc[3][0]);
            acc[0][1] = ffma2(z0, w1, acc[0][1]);
            acc[1][1] = ffma2(z1, w1, acc[1][1]);
            acc[2][1] = ffma2(z2, w1, acc[2][1]);
            acc[3][1] = ffma2(z3, w1, acc[3][1]);
            acc[0][2] = ffma2(z0, w2, acc[0][2]);
            acc[1][2] = ffma2(z1, w2, acc[1][2]);
            acc[2][2] = ffma2(z2, w2, acc[2][2]);
            acc[3][2] = ffma2(z3, w2, acc[3][2]);
        }
        #pragma unroll
        for (int cc = 0; cc < 3; cc++) {
            if (valid[cc]) {
                #pragma unroll
                for (int r = 0; r < 4; r++) {
                    float lo, hi;
                    unpack2(acc[r][cc], lo, hi);
                    if (relu) { lo = fmaxf(lo, 0.f); hi = fmaxf(hi, 0.f); }
                    sout[(c0[cc] + 0) * RS + r0 + r] = lo;
                    sout[(c0[cc] + 1) * RS + r0 + r] = hi;
                }
            }
        }
        __syncwarp();
    };

    gemm(zb, ZDIM, W1, b1, bb, true);
    gemm(bb, HID,  W2, b2, zb, true);
    gemm(zb, HID,  W3, b3, bb, true);
    gemm(bb, HID,  W4, b4, zb, true);
    gemm(zb, HID,  W5, b5, bb, true);

    // ======================= Heads: move[5], mark[1] ========================
    // 24 work items per warp (4 rows x 6 outputs), lanes 0..23.
    if (lane < 24) {
        const int r  = lane / 6;   // row within warp group (0..3)
        const int cc = lane % 6;   // 0..4 move, 5 mark
        const int row = rowbase + r0 + r;
        const float* zz = bb + r0 + r;
        if (cc < 5) {
            float a = bm[cc];
            #pragma unroll 4
            for (int k = 0; k < HID; k++) a = fmaf(zz[k * RS], Wm[k * 5 + cc], a);
            out[row * 5 + cc] = a;
        } else {
            float a = bmk[0];
            #pragma unroll 4
            for (int k = 0; k < HID; k++) a = fmaf(zz[k * RS], Wmk[k], a);
            out[(long long)B * 5 + row] = a;
        }
    }
}

extern "C" void kernel_launch(void* const* d_in, const int* in_sizes, int n_in,
                              void* d_out, int out_size) {
    const float* x   = (const float*)d_in[0];
    const float* Wp  = (const float*)d_in[1];
    const float* bp  = (const float*)d_in[2];
    const float* Wq  = (const float*)d_in[3];
    const float* Wk  = (const float*)d_in[4];
    const float* Wv  = (const float*)d_in[5];
    const float* W1  = (const float*)d_in[6];
    const float* b1  = (const float*)d_in[7];
    const float* W2  = (const float*)d_in[8];
    const float* b2  = (const float*)d_in[9];
    const float* W3  = (const float*)d_in[10];
    const float* b3  = (const float*)d_in[11];
    const float* W4  = (const float*)d_in[12];
    const float* b4  = (const float*)d_in[13];
    const float* W5  = (const float*)d_in[14];
    const float* b5  = (const float*)d_in[15];
    const float* Wm  = (const float*)d_in[16];
    const float* bm  = (const float*)d_in[17];
    const float* Wmk = (const float*)d_in[18];
    const float* bmk = (const float*)d_in[19];
    float* out = (float*)d_out;

    const int B = in_sizes[0] / OBS;            // 131072
    const int smem_bytes = SMEM_FLOATS * 4;     // ~86.5 KB

    cudaFuncSetAttribute(actor_kernel,
                         cudaFuncAttributeMaxDynamicSharedMemorySize,
                         smem_bytes);

    actor_kernel<<<B / TILE_B, 256, smem_bytes>>>(
        x, Wp, bp, Wq, Wk, Wv,
        W1, b1, W2, b2, W3, b3, W4, b4, W5, b5,
        Wm, bm, Wmk, bmk, out, B);
}

// round 4
// speedup vs baseline: 1.7130x; 1.2574x over previous
#include <cuda_runtime.h>
#include <cstdint>

#define FULL_MASK 0xFFFFFFFFu
typedef unsigned long long ull;

// ---------------- packed f32x2 helpers (sm_103a) ----------------
__device__ __forceinline__ ull pack2(float lo, float hi) {
    ull r; asm("mov.b64 %0, {%1, %2};" : "=l"(r) : "f"(lo), "f"(hi)); return r;
}
__device__ __forceinline__ void unpack2(ull v, float& lo, float& hi) {
    asm("mov.b64 {%0, %1}, %2;" : "=f"(lo), "=f"(hi) : "l"(v));
}
__device__ __forceinline__ ull ffma2(ull a, ull b, ull c) {
    ull d; asm("fma.rn.f32x2 %0, %1, %2, %3;" : "=l"(d) : "l"(a), "l"(b), "l"(c)); return d;
}

// ---------------- model constants ----------------
__constant__ int FOFF[23] = {0,4,8,12,16,20,24,28,32,36,40,44,48,50,52,53,57,58,59,60,61,62,63};
__constant__ int FDIM[23] = {4,4,4,4,4,4,4,4,4,4,4,4, 2, 2, 1, 4, 1, 1, 1, 1, 1, 1, 2};

static constexpr int OBS  = 65;
static constexpr int NF   = 23;
static constexpr int EMB  = 10;
static constexpr int ZDIM = 230;
static constexpr int HID  = 164;
static constexpr int TILE_B = 32;     // rows per CTA; 4 pairs x 8 rows
static constexpr int RSW  = 232;      // activation row stride (floats), 16B-aligned

// packed weight layout: per layer, [2 halves x 3 slots][KC chunks][32 lanes][4 k]
// cols padded 164->192 (zero), K padded to x4 (zero rows).
static constexpr int LOFF1 = 0;               // L1: 192 x 232
static constexpr int LOFF2 = 44544;           // L2..L5: 192 x 168 each
static constexpr int LOFF3 = 76800;
static constexpr int LOFF4 = 109056;
static constexpr int LOFF5 = 141312;
static constexpr int WP_TOTAL = 173568;

__device__ float g_wp[WP_TOTAL];
__device__ float g_bp[5 * 192];
__device__ float g_wh[6 * 168];
__device__ float g_bh[6];

// ======================= weight packing kernel =========================
__global__ void pack_kernel(
    const float* __restrict__ W1, const float* __restrict__ W2,
    const float* __restrict__ W3, const float* __restrict__ W4,
    const float* __restrict__ W5,
    const float* __restrict__ b1, const float* __restrict__ b2,
    const float* __restrict__ b3, const float* __restrict__ b4,
    const float* __restrict__ b5,
    const float* __restrict__ Wm, const float* __restrict__ bm,
    const float* __restrict__ Wmk, const float* __restrict__ bmk)
{
    const int k = blockIdx.x;    // 0..231
    const int l = blockIdx.y;    // 0..5 (5 = heads)
    const int c = threadIdx.x;   // 0..191
    if (l < 5) {
        const int KPl = (l == 0) ? 232 : 168;
        if (k >= KPl) return;
        const int Kl  = (l == 0) ? 230 : 164;
        const int KCl = KPl / 4;
        const float* Ws = (l == 0) ? W1 : (l == 1) ? W2 : (l == 2) ? W3 : (l == 3) ? W4 : W5;
        const float* bs = (l == 0) ? b1 : (l == 1) ? b2 : (l == 2) ? b3 : (l == 3) ? b4 : b5;
        const int loff  = (l == 0) ? LOFF1 : (l == 1) ? LOFF2 : (l == 2) ? LOFF3
                         : (l == 3) ? LOFF4 : LOFF5;
        const float v = (c < HID && k < Kl) ? Ws[k * HID + c] : 0.f;
        const int h = c / 96, s = (c % 96) / 32, lane = c % 32;
        g_wp[loff + ((h * 3 + s) * KCl + (k >> 2)) * 128 + lane * 4 + (k & 3)] = v;
        if (k == 0) g_bp[l * 192 + c] = (c < HID) ? bs[c] : 0.f;
    } else {
        if (k >= 168 || c >= 6) return;
        g_wh[c * 168 + k] = (k < HID) ? ((c < 5) ? Wm[k * 5 + c] : Wmk[k]) : 0.f;
        if (k == 0) g_bh[c] = (c < 5) ? bm[c] : bmk[0];
    }
}

// ======================= pair GEMM (8 rows x 96 cols per warp) ==========
template<int KC>
__device__ __forceinline__ void gemm_pair(
    const float* __restrict__ bin, float* __restrict__ bout,
    const float* __restrict__ wl, const float* __restrict__ bp,
    int half, int lane, int barid)
{
    ull acc[8][3];
    int c[3];
    #pragma unroll
    for (int s = 0; s < 3; s++) {
        c[s] = 96 * half + 32 * s + lane;
        const ull a0 = pack2(bp[c[s]], 0.f);
        #pragma unroll
        for (int r = 0; r < 8; r++) acc[r][s] = a0;
    }
    const float4* wq0 = ((const float4*)wl) + (half * 3 + 0) * KC * 32 + lane;
    const float4* wq1 = ((const float4*)wl) + (half * 3 + 1) * KC * 32 + lane;
    const float4* wq2 = ((const float4*)wl) + (half * 3 + 2) * KC * 32 + lane;

    #pragma unroll 2
    for (int kc = 0; kc < KC; kc++) {
        const float4 wv0 = wq0[kc * 32];
        const float4 wv1 = wq1[kc * 32];
        const float4 wv2 = wq2[kc * 32];
        const ull* w0 = (const ull*)&wv0;
        const ull* w1 = (const ull*)&wv1;
        const ull* w2 = (const ull*)&wv2;
        #pragma unroll
        for (int r = 0; r < 8; r++) {
            const float4 zv = ((const float4*)(bin + r * RSW))[kc];  // broadcast
            const ull* zp = (const ull*)&zv;
            acc[r][0] = ffma2(zp[0], w0[0], acc[r][0]);
            acc[r][0] = ffma2(zp[1], w0[1], acc[r][0]);
            acc[r][1] = ffma2(zp[0], w1[0], acc[r][1]);
            acc[r][1] = ffma2(zp[1], w1[1], acc[r][1]);
            acc[r][2] = ffma2(zp[0], w2[0], acc[r][2]);
            acc[r][2] = ffma2(zp[1], w2[1], acc[r][2]);
        }
    }
    #pragma unroll
    for (int s = 0; s < 3; s++) {
        if (c[s] < HID) {
            #pragma unroll
            for (int r = 0; r < 8; r++) {
                float lo, hi; unpack2(acc[r][s], lo, hi);
                bout[r * RSW + c[s]] = fmaxf(lo + hi, 0.f);
            }
        }
    }
    asm volatile("bar.sync %0, 64;" :: "r"(barid) : "memory");
}

// ======================= main kernel ====================================
static constexpr int PAIRBUF = 2 * 8 * RSW;        // 3712 floats per pair
static constexpr int SMEM_FLOATS = 4 * PAIRBUF;    // 14848 (~58 KB)

__global__ void __launch_bounds__(256, 2)
actor_kernel(const float* __restrict__ x,
             const float* __restrict__ Wp, const float* __restrict__ bpj,
             const float* __restrict__ Wq, const float* __restrict__ Wk,
             const float* __restrict__ Wv,
             float* __restrict__ out, int B)
{
    extern __shared__ float sm[];
    const int tid  = threadIdx.x;
    const int w    = tid >> 5;
    const int lane = tid & 31;
    const int pair = w >> 1;
    const int half = w & 1;
    const int barid = 1 + pair;

    float* bufA = sm + pair * PAIRBUF;
    float* bufB = bufA + 8 * RSW;
    // phase-1 scratch overlays bufB (per-warp 800-float region)
    float* scr = bufB + half * 800;
    float* xb = scr;            // 68
    float* qb = scr + 68;       // 232
    float* kb = qb + 232;       // 232
    float* vb = kb + 232;       // 232
    float* ob = vb + 232;       // 32   (total 796)

    const int rowbase = blockIdx.x * TILE_B + pair * 8;

    // ======================= Phase 1: proj + attention ==================
    const float inv_sqrt10 = 0.31622776601683794f;
    for (int rr = 0; rr < 4; rr++) {
        const int lr  = half * 4 + rr;
        const int row = rowbase + lr;
        float* hrow = bufA + lr * RSW;
        for (int i = lane; i < OBS; i += 32) xb[i] = x[row * OBS + i];
        __syncwarp();
        // block-diagonal projection -> h[230] (in place in bufA)
        for (int idx = lane; idx < ZDIM; idx += 32) {
            const int f   = idx / 10;
            const int off = FOFF[f];
            const int dim = FDIM[f];
            float a = bpj[idx];
            for (int d = 0; d < dim; d++)
                a = fmaf(xb[off + d], Wp[(off + d) * ZDIM + idx], a);
            hrow[idx] = a;
        }
        __syncwarp();
        // q, k, v
        for (int idx = lane; idx < ZDIM; idx += 32) {
            const int i = idx / 10;
            const int e = idx - i * 10;
            float aq = 0.f, ak = 0.f, av = 0.f;
            #pragma unroll
            for (int d = 0; d < 10; d++) {
                const float hv = hrow[i * 10 + d];
                aq = fmaf(hv, Wq[d * 10 + e], aq);
                ak = fmaf(hv, Wk[d * 10 + e], ak);
                av = fmaf(hv, Wv[d * 10 + e], av);
            }
            qb[idx] = aq; kb[idx] = ak; vb[idx] = av;
        }
        __syncwarp();
        // attention per query token
        for (int i = 0; i < NF; i++) {
            float lg = -1e30f;
            if (lane < NF) {
                float a = 0.f;
                #pragma unroll
                for (int e = 0; e < 10; e++)
                    a = fmaf(qb[i * 10 + e], kb[lane * 10 + e], a);
                lg = a * inv_sqrt10;
            }
            float m = lg;
            #pragma unroll
            for (int o = 16; o; o >>= 1) m = fmaxf(m, __shfl_xor_sync(FULL_MASK, m, o));
            float p = (lane < NF) ? __expf(lg - m) : 0.f;
            float s = p;
            #pragma unroll
            for (int o = 16; o; o >>= 1) s += __shfl_xor_sync(FULL_MASK, s, o);
            if (lane < NF) ob[lane] = p / s;
            __syncwarp();
            if (lane < EMB) {
                float c = 0.f;
                #pragma unroll
                for (int j = 0; j < NF; j++)
                    c = fmaf(ob[j], vb[j * 10 + lane], c);
                hrow[i * 10 + lane] += c;   // residual
            }
            __syncwarp();
        }
        if (lane < 2) hrow[230 + lane] = 0.f;   // zero K-pad of bufA
        __syncwarp();
    }

    // both warps done with scratch before anyone writes bufB
    asm volatile("bar.sync %0, 64;" :: "r"(barid) : "memory");

    // zero bufB K-pad [164..168) for this warp's 4 rows (row 7 region is
    // outside the scratch overlay and would otherwise be uninitialized)
    if (lane < 16)
        bufB[(half * 4 + (lane >> 2)) * RSW + 164 + (lane & 3)] = 0.f;

    // ======================= Phase 2: MLP ================================
    gemm_pair<58>(bufA, bufB, g_wp + LOFF1, g_bp,       half, lane, barid);
    gemm_pair<42>(bufB, bufA, g_wp + LOFF2, g_bp + 192, half, lane, barid);
    gemm_pair<42>(bufA, bufB, g_wp + LOFF3, g_bp + 384, half, lane, barid);
    gemm_pair<42>(bufB, bufA, g_wp + LOFF4, g_bp + 576, half, lane, barid);
    gemm_pair<42>(bufA, bufB, g_wp + LOFF5, g_bp + 768, half, lane, barid);

    // ======================= Heads: move[5], mark[1] =====================
    const int t = half * 32 + lane;   // 0..63 within pair
    if (t < 48) {
        const int r = t / 6, o = t % 6;
        const float4* zz = (const float4*)(bufB + r * RSW);
        const float4* wh = (const float4*)(g_wh + o * 168);
        float4 a4 = make_float4(0.f, 0.f, 0.f, 0.f);
        #pragma unroll 2
        for (int kc = 0; kc < 42; kc++) {
            const float4 z = zz[kc];
            const float4 ww = wh[kc];
            a4.x = fmaf(z.x, ww.x, a4.x);
            a4.y = fmaf(z.y, ww.y, a4.y);
            a4.z = fmaf(z.z, ww.z, a4.z);
            a4.w = fmaf(z.w, ww.w, a4.w);
        }
        const float a = g_bh[o] + ((a4.x + a4.y) + (a4.z + a4.w));
        const int row = rowbase + r;
        if (o < 5) out[row * 5 + o] = a;
        else       out[(long long)B * 5 + row] = a;
    }
}

extern "C" void kernel_launch(void* const* d_in, const int* in_sizes, int n_in,
                              void* d_out, int out_size) {
    const float* x   = (const float*)d_in[0];
    const float* Wp  = (const float*)d_in[1];
    const float* bp  = (const float*)d_in[2];
    const float* Wq  = (const float*)d_in[3];
    const float* Wk  = (const float*)d_in[4];
    const float* Wv  = (const float*)d_in[5];
    const float* W1  = (const float*)d_in[6];
    const float* b1  = (const float*)d_in[7];
    const float* W2  = (const float*)d_in[8];
    const float* b2  = (const float*)d_in[9];
    const float* W3  = (const float*)d_in[10];
    const float* b3  = (const float*)d_in[11];
    const float* W4  = (const float*)d_in[12];
    const float* b4  = (const float*)d_in[13];
    const float* W5  = (const float*)d_in[14];
    const float* b5  = (const float*)d_in[15];
    const float* Wm  = (const float*)d_in[16];
    const float* bm  = (const float*)d_in[17];
    const float* Wmk = (const float*)d_in[18];
    const float* bmk = (const float*)d_in[19];
    float* out = (float*)d_out;

    const int B = in_sizes[0] / OBS;
    const int smem_bytes = SMEM_FLOATS * 4;

    cudaFuncSetAttribute(actor_kernel,
                         cudaFuncAttributeMaxDynamicSharedMemorySize,
                         smem_bytes);

    pack_kernel<<<dim3(232, 6), 192>>>(W1, W2, W3, W4, W5,
                                       b1, b2, b3, b4, b5,
                                       Wm, bm, Wmk, bmk);
    actor_kernel<<<B / TILE_B, 256, smem_bytes>>>(
        x, Wp, bp, Wq, Wk, Wv, out, B);
}

// round 5
// speedup vs baseline: 2.6424x; 1.5426x over previous
#include <cuda_runtime.h>
#include <cstdint>

#define FULL_MASK 0xFFFFFFFFu
typedef unsigned long long ull;

// ---------------- packed f32x2 helpers (sm_103a) ----------------
__device__ __forceinline__ ull pack2(float lo, float hi) {
    ull r; asm("mov.b64 %0, {%1, %2};" : "=l"(r) : "f"(lo), "f"(hi)); return r;
}
__device__ __forceinline__ void unpack2(ull v, float& lo, float& hi) {
    asm("mov.b64 {%0, %1}, %2;" : "=f"(lo), "=f"(hi) : "l"(v));
}
__device__ __forceinline__ ull ffma2(ull a, ull b, ull c) {
    ull d; asm("fma.rn.f32x2 %0, %1, %2, %3;" : "=l"(d) : "l"(a), "l"(b), "l"(c)); return d;
}

// ---------------- model constants ----------------
__constant__ int FOFF[23] = {0,4,8,12,16,20,24,28,32,36,40,44,48,50,52,53,57,58,59,60,61,62,63};
__constant__ int FDIM[23] = {4,4,4,4,4,4,4,4,4,4,4,4, 2, 2, 1, 4, 1, 1, 1, 1, 1, 1, 2};

static constexpr int OBS  = 65;
static constexpr int NF   = 23;
static constexpr int ZDIM = 230;
static constexpr int HID  = 164;
static constexpr int TILE_B = 32;     // rows per CTA; 4 pairs x 8 rows
static constexpr int RSW  = 232;      // activation row stride (floats), 16B-aligned

// packed MLP weights: per layer, [2 halves x 3 slots][KC chunks][32 lanes][4 k]
static constexpr int LOFF1 = 0;               // L1: 192 x 232
static constexpr int LOFF2 = 44544;           // L2..L5: 192 x 168 each
static constexpr int LOFF3 = 76800;
static constexpr int LOFF4 = 109056;
static constexpr int LOFF5 = 141312;
static constexpr int WP_TOTAL = 173568;

__device__ float g_wp[WP_TOTAL];
__device__ float g_bp[5 * 192];
__device__ float g_wh[6 * 168];
__device__ float g_bh[6];
// phase-1 packed weights
__device__ __align__(16) float g_wproj[NF * 10 * 4];  // [tok][e][d], shift-adjusted
__device__ __align__(16) float g_wqkv[10 * 32];       // [d][ q0..9 k0..9 v0..9 0 0 ]
__device__ int g_offadj[32];

// ======================= weight packing kernel =========================
__global__ void pack_kernel(
    const float* __restrict__ W1, const float* __restrict__ W2,
    const float* __restrict__ W3, const float* __restrict__ W4,
    const float* __restrict__ W5,
    const float* __restrict__ b1, const float* __restrict__ b2,
    const float* __restrict__ b3, const float* __restrict__ b4,
    const float* __restrict__ b5,
    const float* __restrict__ Wm, const float* __restrict__ bm,
    const float* __restrict__ Wmk, const float* __restrict__ bmk,
    const float* __restrict__ Wp,
    const float* __restrict__ Wq, const float* __restrict__ Wk,
    const float* __restrict__ Wv)
{
    const int k = blockIdx.x;    // 0..231
    const int l = blockIdx.y;    // 0..7
    const int c = threadIdx.x;   // 0..191
    if (l < 5) {
        const int KPl = (l == 0) ? 232 : 168;
        if (k >= KPl) return;
        const int Kl  = (l == 0) ? 230 : 164;
        const int KCl = KPl / 4;
        const float* Ws = (l == 0) ? W1 : (l == 1) ? W2 : (l == 2) ? W3 : (l == 3) ? W4 : W5;
        const float* bs = (l == 0) ? b1 : (l == 1) ? b2 : (l == 2) ? b3 : (l == 3) ? b4 : b5;
        const int loff  = (l == 0) ? LOFF1 : (l == 1) ? LOFF2 : (l == 2) ? LOFF3
                         : (l == 3) ? LOFF4 : LOFF5;
        const float v = (c < HID && k < Kl) ? Ws[k * HID + c] : 0.f;
        const int h = c / 96, s = (c % 96) / 32, lane = c % 32;
        g_wp[loff + ((h * 3 + s) * KCl + (k >> 2)) * 128 + lane * 4 + (k & 3)] = v;
        if (k == 0) g_bp[l * 192 + c] = (c < HID) ? bs[c] : 0.f;
    } else if (l == 5) {
        if (k >= 168 || c >= 6) return;
        g_wh[c * 168 + k] = (k < HID) ? ((c < 5) ? Wm[k * 5 + c] : Wmk[k]) : 0.f;
        if (k == 0) g_bh[c] = (c < 5) ? bm[c] : bmk[0];
    } else if (l == 6) {
        // g_wproj[tok][e][d]: shift-adjusted gather of masked W_proj
        if (k < ZDIM && c < 4) {
            const int i = k / 10;                // token
            const int off  = FOFF[i];
            const int dim  = FDIM[i];
            const int offa = (off < 61) ? off : 61;
            const int shift = off - offa;
            const int d = c;
            float v = 0.f;
            if (d >= shift && (d - shift) < dim)
                v = Wp[(offa + d) * ZDIM + k];
            g_wproj[k * 4 + d] = v;
        }
        if (c == 4 && k < 32)
            g_offadj[k] = (k < NF) ? ((FOFF[k] < 61) ? FOFF[k] : 61) : 0;
    } else {
        // g_wqkv[d][32]
        if (k < 10 && c < 32) {
            float v = 0.f;
            if (c < 10)      v = Wq[k * 10 + c];
            else if (c < 20) v = Wk[k * 10 + (c - 10)];
            else if (c < 30) v = Wv[k * 10 + (c - 20)];
            g_wqkv[k * 32 + c] = v;
        }
    }
}

// ======================= pair GEMM (8 rows x 96 cols per warp) ==========
template<int KC>
__device__ __forceinline__ void gemm_pair(
    const float* __restrict__ bin, float* __restrict__ bout,
    const float* __restrict__ wl, const float* __restrict__ bp,
    int half, int lane, int barid)
{
    ull acc[8][3];
    int c[3];
    #pragma unroll
    for (int s = 0; s < 3; s++) {
        c[s] = 96 * half + 32 * s + lane;
        const ull a0 = pack2(bp[c[s]], 0.f);
        #pragma unroll
        for (int r = 0; r < 8; r++) acc[r][s] = a0;
    }
    const float4* wq0 = ((const float4*)wl) + (half * 3 + 0) * KC * 32 + lane;
    const float4* wq1 = ((const float4*)wl) + (half * 3 + 1) * KC * 32 + lane;
    const float4* wq2 = ((const float4*)wl) + (half * 3 + 2) * KC * 32 + lane;

    #pragma unroll 2
    for (int kc = 0; kc < KC; kc++) {
        const float4 wv0 = wq0[kc * 32];
        const float4 wv1 = wq1[kc * 32];
        const float4 wv2 = wq2[kc * 32];
        const ull* w0 = (const ull*)&wv0;
        const ull* w1 = (const ull*)&wv1;
        const ull* w2 = (const ull*)&wv2;
        #pragma unroll
        for (int r = 0; r < 8; r++) {
            const float4 zv = ((const float4*)(bin + r * RSW))[kc];  // broadcast
            const ull* zp = (const ull*)&zv;
            acc[r][0] = ffma2(zp[0], w0[0], acc[r][0]);
            acc[r][0] = ffma2(zp[1], w0[1], acc[r][0]);
            acc[r][1] = ffma2(zp[0], w1[0], acc[r][1]);
            acc[r][1] = ffma2(zp[1], w1[1], acc[r][1]);
            acc[r][2] = ffma2(zp[0], w2[0], acc[r][2]);
            acc[r][2] = ffma2(zp[1], w2[1], acc[r][2]);
        }
    }
    #pragma unroll
    for (int s = 0; s < 3; s++) {
        if (c[s] < HID) {
            #pragma unroll
            for (int r = 0; r < 8; r++) {
                float lo, hi; unpack2(acc[r][s], lo, hi);
                bout[r * RSW + c[s]] = fmaxf(lo + hi, 0.f);
            }
        }
    }
    asm volatile("bar.sync %0, 64;" :: "r"(barid) : "memory");
}

// ======================= main kernel ====================================
static constexpr int PAIRBUF = 2 * 8 * RSW;        // 3712 floats per pair
static constexpr int SMEM_FLOATS = 4 * PAIRBUF;    // 14848 (~58 KB)

__global__ void __launch_bounds__(256, 2)
actor_kernel(const float* __restrict__ x,
             const float* __restrict__ bpj,
             float* __restrict__ out, int B)
{
    extern __shared__ float sm[];
    const int tid  = threadIdx.x;
    const int w    = tid >> 5;
    const int lane = tid & 31;
    const int pair = w >> 1;
    const int half = w & 1;
    const int barid = 1 + pair;

    float* bufA = sm + pair * PAIRBUF;
    float* bufB = bufA + 8 * RSW;
    // phase-1 scratch overlays bufB: per-warp k/v staging
    float* scr = bufB + half * 576;
    float* kb = scr;          // [23][12]
    float* vb = scr + 288;    // [23][12]

    const int rowbase = blockIdx.x * TILE_B + pair * 8;
    const float inv_sqrt10 = 0.31622776601683794f;

    // ============== Phase 1: token-per-lane proj + attention ============
    const int tok = (lane < NF) ? lane : 0;
    const int offa = g_offadj[tok];
    float4 wpj[10];
    float  bq[10];
    #pragma unroll
    for (int e = 0; e < 10; e++) wpj[e] = ((const float4*)g_wproj)[tok * 10 + e];
    {
        const float2* b2 = (const float2*)(bpj + tok * 10);
        #pragma unroll
        for (int u = 0; u < 5; u++) { float2 t = b2[u]; bq[2*u] = t.x; bq[2*u+1] = t.y; }
    }

    #pragma unroll 1
    for (int rr = 0; rr < 4; rr++) {
        const int lr  = half * 4 + rr;
        const int row = rowbase + lr;
        float* zrow = bufA + lr * RSW;

        const float* xr = x + (long long)row * OBS + offa;
        const float x0 = xr[0], x1 = xr[1], x2 = xr[2], x3 = xr[3];

        float h[10];
        #pragma unroll
        for (int e = 0; e < 10; e++)
            h[e] = fmaf(x3, wpj[e].w, fmaf(x2, wpj[e].z,
                   fmaf(x1, wpj[e].y, fmaf(x0, wpj[e].x, bq[e]))));

        // qkv in registers
        float q[10], kk[10], vv[10];
        #pragma unroll
        for (int e = 0; e < 10; e++) { q[e] = 0.f; kk[e] = 0.f; vv[e] = 0.f; }
        #pragma unroll
        for (int d = 0; d < 10; d++) {
            float wf[32];
            #pragma unroll
            for (int u = 0; u < 8; u++)
                *(float4*)(wf + 4 * u) = ((const float4*)(g_wqkv + d * 32))[u];
            const float hd = h[d];
            #pragma unroll
            for (int e = 0; e < 10; e++) {
                q[e]  = fmaf(hd, wf[e],      q[e]);
                kk[e] = fmaf(hd, wf[10 + e], kk[e]);
                vv[e] = fmaf(hd, wf[20 + e], vv[e]);
            }
        }
        // stage k,v to per-warp smem (stride 12 -> 16B-aligned rows)
        if (lane < NF) {
            float2* ks = (float2*)(kb + tok * 12);
            float2* vs = (float2*)(vb + tok * 12);
            #pragma unroll
            for (int u = 0; u < 5; u++) {
                ks[u] = make_float2(kk[2*u], kk[2*u+1]);
                vs[u] = make_float2(vv[2*u], vv[2*u+1]);
            }
        }
        __syncwarp();

        // fused logits/exp/ctx (lane-local softmax, normalize at end)
        float ssum = 0.f;
        float ctx[10];
        #pragma unroll
        for (int e = 0; e < 10; e++) ctx[e] = 0.f;
        #pragma unroll
        for (int j = 0; j < NF; j++) {
            const float* kj = kb + j * 12;
            const float4 ka = *(const float4*)kj;
            const float4 kbv = *(const float4*)(kj + 4);
            const float2 kc = *(const float2*)(kj + 8);
            float dt;
            dt = q[0] * ka.x;
            dt = fmaf(q[1], ka.y, dt);
            dt = fmaf(q[2], ka.z, dt);
            dt = fmaf(q[3], ka.w, dt);
            dt = fmaf(q[4], kbv.x, dt);
            dt = fmaf(q[5], kbv.y, dt);
            dt = fmaf(q[6], kbv.z, dt);
            dt = fmaf(q[7], kbv.w, dt);
            dt = fmaf(q[8], kc.x, dt);
            dt = fmaf(q[9], kc.y, dt);
            const float pe = __expf(dt * inv_sqrt10);
            ssum += pe;
            const float* vj = vb + j * 12;
            const float4 va = *(const float4*)vj;
            const float4 vbv = *(const float4*)(vj + 4);
            const float2 vc = *(const float2*)(vj + 8);
            ctx[0] = fmaf(pe, va.x, ctx[0]);
            ctx[1] = fmaf(pe, va.y, ctx[1]);
            ctx[2] = fmaf(pe, va.z, ctx[2]);
            ctx[3] = fmaf(pe, va.w, ctx[3]);
            ctx[4] = fmaf(pe, vbv.x, ctx[4]);
            ctx[5] = fmaf(pe, vbv.y, ctx[5]);
            ctx[6] = fmaf(pe, vbv.z, ctx[6]);
            ctx[7] = fmaf(pe, vbv.w, ctx[7]);
            ctx[8] = fmaf(pe, vc.x, ctx[8]);
            ctx[9] = fmaf(pe, vc.y, ctx[9]);
        }
        const float rs = __fdividef(1.f, ssum);
        if (lane < NF) {
            float2* zs = (float2*)(zrow + tok * 10);
            #pragma unroll
            for (int u = 0; u < 5; u++)
                zs[u] = make_float2(fmaf(ctx[2*u],   rs, h[2*u]),
                                    fmaf(ctx[2*u+1], rs, h[2*u+1]));
        }
        if (lane == NF) { zrow[230] = 0.f; zrow[231] = 0.f; }  // K-pad
        __syncwarp();
    }

    // both warps done with scratch before anyone writes bufB
    asm volatile("bar.sync %0, 64;" :: "r"(barid) : "memory");

    // zero bufB K-pad [164..168) for this warp's 4 rows
    if (lane < 16)
        bufB[(half * 4 + (lane >> 2)) * RSW + 164 + (lane & 3)] = 0.f;

    // ======================= Phase 2: MLP ================================
    gemm_pair<58>(bufA, bufB, g_wp + LOFF1, g_bp,       half, lane, barid);
    gemm_pair<42>(bufB, bufA, g_wp + LOFF2, g_bp + 192, half, lane, barid);
    gemm_pair<42>(bufA, bufB, g_wp + LOFF3, g_bp + 384, half, lane, barid);
    gemm_pair<42>(bufB, bufA, g_wp + LOFF4, g_bp + 576, half, lane, barid);
    gemm_pair<42>(bufA, bufB, g_wp + LOFF5, g_bp + 768, half, lane, barid);

    // ======================= Heads: move[5], mark[1] =====================
    const int t = half * 32 + lane;   // 0..63 within pair
    if (t < 48) {
        const int r = t / 6, o = t % 6;
        const float4* zz = (const float4*)(bufB + r * RSW);
        const float4* wh = (const float4*)(g_wh + o * 168);
        float4 a4 = make_float4(0.f, 0.f, 0.f, 0.f);
        #pragma unroll 2
        for (int kc = 0; kc < 42; kc++) {
            const float4 z = zz[kc];
            const float4 ww = wh[kc];
            a4.x = fmaf(z.x, ww.x, a4.x);
            a4.y = fmaf(z.y, ww.y, a4.y);
            a4.z = fmaf(z.z, ww.z, a4.z);
            a4.w = fmaf(z.w, ww.w, a4.w);
        }
        const float a = g_bh[o] + ((a4.x + a4.y) + (a4.z + a4.w));
        const int row = rowbase + r;
        if (o < 5) out[row * 5 + o] = a;
        else       out[(long long)B * 5 + row] = a;
    }
}

extern "C" void kernel_launch(void* const* d_in, const int* in_sizes, int n_in,
                              void* d_out, int out_size) {
    const float* x   = (const float*)d_in[0];
    const float* Wp  = (const float*)d_in[1];
    const float* bp  = (const float*)d_in[2];
    const float* Wq  = (const float*)d_in[3];
    const float* Wk  = (const float*)d_in[4];
    const float* Wv  = (const float*)d_in[5];
    const float* W1  = (const float*)d_in[6];
    const float* b1  = (const float*)d_in[7];
    const float* W2  = (const float*)d_in[8];
    const float* b2  = (const float*)d_in[9];
    const float* W3  = (const float*)d_in[10];
    const float* b3  = (const float*)d_in[11];
    const float* W4  = (const float*)d_in[12];
    const float* b4  = (const float*)d_in[13];
    const float* W5  = (const float*)d_in[14];
    const float* b5  = (const float*)d_in[15];
    const float* Wm  = (const float*)d_in[16];
    const float* bm  = (const float*)d_in[17];
    const float* Wmk = (const float*)d_in[18];
    const float* bmk = (const float*)d_in[19];
    float* out = (float*)d_out;

    const int B = in_sizes[0] / OBS;
    const int smem_bytes = SMEM_FLOATS * 4;

    cudaFuncSetAttribute(actor_kernel,
                         cudaFuncAttributeMaxDynamicSharedMemorySize,
                         smem_bytes);

    pack_kernel<<<dim3(232, 8), 192>>>(W1, W2, W3, W4, W5,
                                       b1, b2, b3, b4, b5,
                                       Wm, bm, Wmk, bmk,
                                       Wp, Wq, Wk, Wv);
    actor_kernel<<<B / TILE_B, 256, smem_bytes>>>(x, bp, out, B);
}